// round 15
// baseline (speedup 1.0000x reference)
#include <cuda_runtime.h>
#include <cuda_fp16.h>
#include <stdint.h>
#include <math.h>

// ---------------- problem constants ----------------
#define NROWS 65536
#define NCENT 512
#define DIM   128
#define BM    128               // rows per CTA
#define BN    128               // centroids per tile
#define NTILES (NCENT / BN)     // 4
#define NTHREADS 256
#define NBLK   (NROWS / BM)     // 512

// ---------------- smem layout (uint32 word offsets) ----------------
// A fragments (fp16 pairs): 8 mt x 8 ks x 33(32 lanes + pad) x 4 words
#define A_WORDS   (8 * 8 * 33 * 4)            // 8448
#define M2_W      A_WORDS
#define Z2_W      (M2_W + NCENT)
#define SH_W      (Z2_W + BM)
#define SMEM_BYTES ((SH_W + 16) * 4)          // ~36.5 KB -> 2 CTAs/SM (reg-limited)

#define BT_WORDS  (8 * 8 * 32 * 4)            // 8192 words = 32KB per tile (nt-pair packed)

// ---------------- device scratch (no cudaMalloc allowed) ----------------
__device__ float g_m2[NCENT];
__device__ float g_partials[NBLK];
__device__ unsigned g_done = 0;   // atomicInc-wrap counter, self-resets each launch
// mu fp16 B-fragment images, nt-pair packed:
// word = ((pr*8+ks)*32 + g*4+tg)*4 + half*2 + rg, pr = nt>>1, half = nt&1
__device__ uint4 g_mub[NTILES][BT_WORDS / 4];

// ================= PTX helpers =================
__device__ __forceinline__ uint32_t smem_u32(const void* p) {
    uint32_t a;
    asm("{ .reg .u64 t; cvta.to.shared.u64 t, %1; cvt.u32.u64 %0, t; }"
        : "=r"(a) : "l"(p));
    return a;
}
// D[16x8](f32) += A[16x16](f16) * B[16x8](f16)
__device__ __forceinline__ void mma_fp16(float* d, const uint32_t* a,
                                         uint32_t b0, uint32_t b1) {
    asm volatile(
        "mma.sync.aligned.m16n8k16.row.col.f32.f16.f16.f32 "
        "{%0,%1,%2,%3}, {%4,%5,%6,%7}, {%8,%9}, {%0,%1,%2,%3};"
        : "+f"(d[0]), "+f"(d[1]), "+f"(d[2]), "+f"(d[3])
        : "r"(a[0]), "r"(a[1]), "r"(a[2]), "r"(a[3]), "r"(b0), "r"(b1));
}
__device__ __forceinline__ float warp_sum(float p) {
#pragma unroll
    for (int o = 16; o; o >>= 1) p += __shfl_xor_sync(0xffffffffu, p, o);
    return p;
}
__device__ __forceinline__ uint32_t h2bits(float a, float b) {
    __half2 h = __floats2half2_rn(a, b);
    return *reinterpret_cast<uint32_t*>(&h);
}

// ================= kernel 0: mu -> fp16 B-fragments (nt-pair packed) + m2 ==
__global__ void mu_prep_kernel(const float* __restrict__ mu) {
    const int b = blockIdx.x;                 // 32 blocks
    const int ct = b >> 3, sub = b & 7;
    const int tid = threadIdx.x, w = tid >> 5, lane = tid & 31;
    uint32_t* dst = reinterpret_cast<uint32_t*>(g_mub[ct]);
    const float4* mp = reinterpret_cast<const float4*>(mu);
#pragma unroll
    for (int it = 0; it < 2; ++it) {
        int nl = sub * 16 + w + it * 8;           // local centroid 0..127
        float4 v = mp[(size_t)(ct * BN + nl) * 32 + lane];
        float p = warp_sum(v.x * v.x + v.y * v.y + v.z * v.z + v.w * v.w);
        if (lane == 0) g_m2[ct * BN + nl] = p;
        int ntg = nl >> 3, gg = nl & 7;
        int pr = ntg >> 1, half = ntg & 1;
        float e[4] = { v.x, v.y, v.z, v.w };
#pragma unroll
        for (int p2 = 0; p2 < 2; ++p2) {
            int c  = lane * 4 + 2 * p2;
            int ks = lane >> 2, cc = c & 15;
            int rg = cc >> 3, tg = (cc & 7) >> 1;
            dst[((pr * 8 + ks) * 32 + gg * 4 + tg) * 4 + half * 2 + rg] =
                h2bits(e[2 * p2], e[2 * p2 + 1]);
        }
    }
}

// ================= main kernel: fp16 mma.sync GEMM, B via LDG pipeline =====
__global__ void __launch_bounds__(NTHREADS, 2)
kmeans_mma_kernel(const float* __restrict__ z, float* __restrict__ out) {
    extern __shared__ uint32_t sm[];
    uint32_t* A_s  = sm;
    float* m2_s = reinterpret_cast<float*>(sm + M2_W);
    float* z2_s = reinterpret_cast<float*>(sm + Z2_W);
    float* sh   = reinterpret_cast<float*>(sm + SH_W);

    const int tid = threadIdx.x, w = tid >> 5, lane = tid & 31;
    const int warp_m = w >> 2, warp_n = w & 3;       // 2 x 4 warp grid
    const int g = lane >> 2, tig = lane & 3;
    const int row0 = blockIdx.x * BM;
    const float4* zp = reinterpret_cast<const float4*>(z);

    // per-thread B gmem base (nt-pair packed): two uint4 per ks
    const uint4* Bg0 = &g_mub[0][(((warp_n * 2 + 0) * 8) * 32 + lane) * 4 / 4];
    const uint4* Bg1 = &g_mub[0][(((warp_n * 2 + 1) * 8) * 32 + lane) * 4 / 4];
    // per-(ct,ks) offsets: ct advances BT_WORDS/4 uint4s, ks advances 32 uint4s

    // ---- A staging: z -> fp16 fragment layout + exact fp32 z2 ----
#pragma unroll
    for (int it = 0; it < 16; ++it) {
        int r = w + it * 8;
        float4 v = zp[(size_t)(row0 + r) * 32 + lane];
        float p = warp_sum(v.x * v.x + v.y * v.y + v.z * v.z + v.w * v.w);
        if (lane == 0) z2_s[r] = p;
        int mt = r >> 4, rr = r & 15, gg = rr & 7, jl = rr >> 3;
        float e[4] = { v.x, v.y, v.z, v.w };
#pragma unroll
        for (int p2 = 0; p2 < 2; ++p2) {
            int c  = lane * 4 + 2 * p2;
            int ks = lane >> 2, cc = c & 15;
            int hi = cc >> 3, tg = (cc & 7) >> 1;
            A_s[((mt * 8 + ks) * 33 + gg * 4 + tg) * 4 + jl + 2 * hi] =
                h2bits(e[2 * p2], e[2 * p2 + 1]);
        }
    }
    for (int i = tid; i < NCENT; i += NTHREADS) m2_s[i] = g_m2[i];
    __syncthreads();              // A staged (only barrier before reduction)

    float rowmin[8];
#pragma unroll
    for (int k = 0; k < 8; ++k) rowmin[k] = 3.402823466e38f;

    // ---- barrier-free mainloop: flattened 4 ct x 8 ks, B prefetched 1 ahead ----
    float acc[4][4][4];
#pragma unroll
    for (int mt = 0; mt < 4; ++mt)
#pragma unroll
        for (int nt = 0; nt < 4; ++nt)
#pragma unroll
            for (int q = 0; q < 4; ++q) acc[mt][nt][q] = 0.f;

    uint4 bb0 = Bg0[0], bb1 = Bg1[0];     // (ct=0, ks=0)

#pragma unroll
    for (int it = 0; it < NTILES * 8; ++it) {
        const int ct = it >> 3, ks = it & 7;
        // prefetch next iteration's B fragments
        uint4 nb0, nb1;
        if (it + 1 < NTILES * 8) {
            const int nct = (it + 1) >> 3, nks = (it + 1) & 7;
            const int off = nct * (BT_WORDS / 4) + nks * 32;
            nb0 = Bg0[off];
            nb1 = Bg1[off];
        }
        // A fragments from smem
        uint32_t a[4][4];
#pragma unroll
        for (int mt = 0; mt < 4; ++mt)
            *reinterpret_cast<uint4*>(a[mt]) = *reinterpret_cast<const uint4*>(
                &A_s[(((warp_m * 4 + mt) * 8 + ks) * 33 + lane) * 4]);
#pragma unroll
        for (int mt = 0; mt < 4; ++mt) {
            mma_fp16(acc[mt][0], a[mt], bb0.x, bb0.y);
            mma_fp16(acc[mt][1], a[mt], bb0.z, bb0.w);
            mma_fp16(acc[mt][2], a[mt], bb1.x, bb1.y);
            mma_fp16(acc[mt][3], a[mt], bb1.z, bb1.w);
        }
        bb0 = nb0; bb1 = nb1;

        if (ks == 7) {
            // ---- epilogue for tile ct: d2 = z2 + m2 - 2*dot, running min ----
            // D frag: c0=(g,2tig) c1=(g,2tig+1) c2=(g+8,2tig) c3=(g+8,2tig+1)
#pragma unroll
            for (int mt = 0; mt < 4; ++mt) {
                int rb = warp_m * 64 + mt * 16 + g;
                float z2a = z2_s[rb], z2b = z2_s[rb + 8];
#pragma unroll
                for (int nt = 0; nt < 4; ++nt) {
                    int cb = ct * BN + warp_n * 32 + nt * 8 + 2 * tig;
                    float m0 = m2_s[cb], m1 = m2_s[cb + 1];
                    rowmin[mt * 2]     = fminf(rowmin[mt * 2],
                                               fmaf(-2.f, acc[mt][nt][0], z2a + m0));
                    rowmin[mt * 2]     = fminf(rowmin[mt * 2],
                                               fmaf(-2.f, acc[mt][nt][1], z2a + m1));
                    rowmin[mt * 2 + 1] = fminf(rowmin[mt * 2 + 1],
                                               fmaf(-2.f, acc[mt][nt][2], z2b + m0));
                    rowmin[mt * 2 + 1] = fminf(rowmin[mt * 2 + 1],
                                               fmaf(-2.f, acc[mt][nt][3], z2b + m1));
                }
            }
#pragma unroll
            for (int mt = 0; mt < 4; ++mt)
#pragma unroll
                for (int nt = 0; nt < 4; ++nt)
#pragma unroll
                    for (int q = 0; q < 4; ++q) acc[mt][nt][q] = 0.f;
        }
    }

    // ---- min across 4 tig lanes, then cross-warp (reuse A_s as red matrix) ----
#pragma unroll
    for (int k = 0; k < 8; ++k) {
        float v = rowmin[k];
        v = fminf(v, __shfl_xor_sync(0xffffffffu, v, 1));
        v = fminf(v, __shfl_xor_sync(0xffffffffu, v, 2));
        rowmin[k] = v;
    }
    float* red = reinterpret_cast<float*>(A_s);
    if (tig == 0) {
#pragma unroll
        for (int mt = 0; mt < 4; ++mt) {
            red[(warp_m * 64 + mt * 16 + g) * 4 + warp_n]     = rowmin[mt * 2];
            red[(warp_m * 64 + mt * 16 + 8 + g) * 4 + warp_n] = rowmin[mt * 2 + 1];
        }
    }
    __syncthreads();

    float dist = 0.f;
    if (tid < BM) {
        float m = fminf(fminf(red[tid * 4], red[tid * 4 + 1]),
                        fminf(red[tid * 4 + 2], red[tid * 4 + 3]));
        dist = sqrtf(fmaxf(m, 0.f));
    }
#pragma unroll
    for (int o = 16; o; o >>= 1) dist += __shfl_down_sync(0xffffffffu, dist, o);
    if (lane == 0) sh[w] = dist;
    __syncthreads();
    if (tid == 0) {
        float s = 0.f;
#pragma unroll
        for (int i = 0; i < 8; i++) s += sh[i];
        g_partials[blockIdx.x] = s;
    }
    __threadfence();

    // ---- fused deterministic final reduction: last block sums all partials ----
    __shared__ unsigned lastflag;
    if (tid == 0) lastflag = atomicInc(&g_done, NBLK - 1);  // wraps back to 0
    __syncthreads();
    if (lastflag == NBLK - 1) {
        __threadfence();
        float v = g_partials[tid] + g_partials[tid + NTHREADS];
#pragma unroll
        for (int o = 16; o; o >>= 1) v += __shfl_down_sync(0xffffffffu, v, o);
        if (lane == 0) sh[w] = v;
        __syncthreads();
        if (tid == 0) {
            float s = 0.f;
#pragma unroll
            for (int i = 0; i < 8; i++) s += sh[i];
            out[0] = s / (float)NROWS;
        }
    }
}

// ---------------------------------------------------------------------------
extern "C" void kernel_launch(void* const* d_in, const int* in_sizes, int n_in,
                              void* d_out, int out_size) {
    const float* z  = (const float*)d_in[0];   // (65536,1,128) contiguous
    const float* mu = (const float*)d_in[1];   // (512,128)
    float* out = (float*)d_out;

    cudaFuncSetAttribute(kmeans_mma_kernel,
                         cudaFuncAttributeMaxDynamicSharedMemorySize, SMEM_BYTES);

    mu_prep_kernel<<<NTILES * 8, 256>>>(mu);
    kmeans_mma_kernel<<<NBLK, NTHREADS, SMEM_BYTES>>>(z, out);
}

// round 17
// speedup vs baseline: 2.0687x; 2.0687x over previous
#include <cuda_runtime.h>
#include <cuda_fp16.h>
#include <stdint.h>
#include <math.h>

// ---------------- problem constants ----------------
#define NROWS 65536
#define NCENT 512
#define DIM   128
#define BM    128               // rows per CTA
#define BN    128               // centroids per tile
#define NTILES (NCENT / BN)     // 4
#define NTHREADS 256
#define NBLK   (NROWS / BM)     // 512

// ---------------- smem layout (uint32 word offsets) ----------------
// A fragments (fp16 pairs): 8 mt x 8 ks x 33(32 lanes + pad) x 4 words
#define A_WORDS   (8 * 8 * 33 * 4)            // 8448
#define BT_WORDS  (8 * 8 * 32 * 4)            // 8192 words = 32KB per tile (nt-pair packed)
#define B_W(b)    (A_WORDS + (b) * BT_WORDS)
#define M2_W      (A_WORDS + 2 * BT_WORDS)    // 24832
#define Z2_W      (M2_W + NCENT)              // 25344
#define SH_W      (Z2_W + BM)                 // 25472
#define SMEM_BYTES ((SH_W + 16) * 4)          // ~99.6 KB -> 2 CTAs/SM

// ---------------- device scratch (no cudaMalloc allowed) ----------------
__device__ float g_m2[NCENT];
__device__ float g_partials[NBLK];
__device__ unsigned g_done = 0;   // atomicInc-wrap counter, self-resets each launch
// mu fp16 B-fragment images, nt-pair packed:
// word = ((pr*8+ks)*32 + g*4+tg)*4 + half*2 + rg, pr = nt>>1, half = nt&1
__device__ uint4 g_mub[NTILES][BT_WORDS / 4];

// ================= PTX helpers =================
__device__ __forceinline__ uint32_t smem_u32(const void* p) {
    uint32_t a;
    asm("{ .reg .u64 t; cvta.to.shared.u64 t, %1; cvt.u32.u64 %0, t; }"
        : "=r"(a) : "l"(p));
    return a;
}
__device__ __forceinline__ void cp_async16(uint32_t s, const void* g) {
    asm volatile("cp.async.cg.shared.global [%0], [%1], 16;" :: "r"(s), "l"(g));
}
#define CP_COMMIT()  asm volatile("cp.async.commit_group;" ::: "memory")
#define CP_WAIT(n)   asm volatile("cp.async.wait_group %0;" :: "n"(n) : "memory")

// D[16x8](f32) += A[16x16](f16) * B[16x8](f16)
__device__ __forceinline__ void mma_fp16(float* d, const uint32_t* a,
                                         uint32_t b0, uint32_t b1) {
    asm volatile(
        "mma.sync.aligned.m16n8k16.row.col.f32.f16.f16.f32 "
        "{%0,%1,%2,%3}, {%4,%5,%6,%7}, {%8,%9}, {%0,%1,%2,%3};"
        : "+f"(d[0]), "+f"(d[1]), "+f"(d[2]), "+f"(d[3])
        : "r"(a[0]), "r"(a[1]), "r"(a[2]), "r"(a[3]), "r"(b0), "r"(b1));
}
__device__ __forceinline__ float warp_sum(float p) {
#pragma unroll
    for (int o = 16; o; o >>= 1) p += __shfl_xor_sync(0xffffffffu, p, o);
    return p;
}
__device__ __forceinline__ uint32_t h2bits(float a, float b) {
    __half2 h = __floats2half2_rn(a, b);
    return *reinterpret_cast<uint32_t*>(&h);
}

// ================= kernel 0: mu -> fp16 B-fragments (nt-pair packed) + m2 ==
__global__ void mu_prep_kernel(const float* __restrict__ mu) {
    const int b = blockIdx.x;                 // 32 blocks
    const int ct = b >> 3, sub = b & 7;
    const int tid = threadIdx.x, w = tid >> 5, lane = tid & 31;
    uint32_t* dst = reinterpret_cast<uint32_t*>(g_mub[ct]);
    const float4* mp = reinterpret_cast<const float4*>(mu);
#pragma unroll
    for (int it = 0; it < 2; ++it) {
        int nl = sub * 16 + w + it * 8;           // local centroid 0..127
        float4 v = mp[(size_t)(ct * BN + nl) * 32 + lane];
        float p = warp_sum(v.x * v.x + v.y * v.y + v.z * v.z + v.w * v.w);
        if (lane == 0) g_m2[ct * BN + nl] = p;
        int ntg = nl >> 3, gg = nl & 7;
        int pr = ntg >> 1, half = ntg & 1;
        float e[4] = { v.x, v.y, v.z, v.w };
#pragma unroll
        for (int p2 = 0; p2 < 2; ++p2) {
            int c  = lane * 4 + 2 * p2;
            int ks = lane >> 2, cc = c & 15;
            int rg = cc >> 3, tg = (cc & 7) >> 1;
            dst[((pr * 8 + ks) * 32 + gg * 4 + tg) * 4 + half * 2 + rg] =
                h2bits(e[2 * p2], e[2 * p2 + 1]);
        }
    }
}

// ================= main kernel: fp16 mma.sync GEMM + min + fused reduce ====
__global__ void __launch_bounds__(NTHREADS, 2)
kmeans_mma_kernel(const float* __restrict__ z, float* __restrict__ out) {
    extern __shared__ uint32_t sm[];
    uint32_t* A_s  = sm;
    float* m2_s = reinterpret_cast<float*>(sm + M2_W);
    float* z2_s = reinterpret_cast<float*>(sm + Z2_W);
    float* sh   = reinterpret_cast<float*>(sm + SH_W);
    const uint32_t sb = smem_u32(sm);

    const int tid = threadIdx.x, w = tid >> 5, lane = tid & 31;
    const int warp_m = w >> 2, warp_n = w & 3;       // 2 x 4 warp grid
    const int g = lane >> 2, tig = lane & 3;
    const int row0 = blockIdx.x * BM;
    const float4* zp = reinterpret_cast<const float4*>(z);

    // ---- prefetch B tile 0 first (overlaps with A staging) ----
    {
        const uint4* src = g_mub[0];
        for (int i = tid; i < BT_WORDS / 4; i += NTHREADS)
            cp_async16(sb + B_W(0) * 4 + i * 16, src + i);
        CP_COMMIT();
    }

    // ---- A staging: z -> fp16 fragment layout + exact fp32 z2 ----
    // A frag: lane g*4+tg holds a_j = halves (row g+8*(j&1), cols 2tg+8*(j>>1)+{0,1})
#pragma unroll
    for (int it = 0; it < 16; ++it) {
        int r = w + it * 8;
        float4 v = zp[(size_t)(row0 + r) * 32 + lane];
        float p = warp_sum(v.x * v.x + v.y * v.y + v.z * v.z + v.w * v.w);
        if (lane == 0) z2_s[r] = p;
        int mt = r >> 4, rr = r & 15, gg = rr & 7, jl = rr >> 3;
        float e[4] = { v.x, v.y, v.z, v.w };
#pragma unroll
        for (int p2 = 0; p2 < 2; ++p2) {
            int c  = lane * 4 + 2 * p2;
            int ks = lane >> 2, cc = c & 15;
            int hi = cc >> 3, tg = (cc & 7) >> 1;
            A_s[((mt * 8 + ks) * 33 + gg * 4 + tg) * 4 + jl + 2 * hi] =
                h2bits(e[2 * p2], e[2 * p2 + 1]);
        }
    }
    for (int i = tid; i < NCENT; i += NTHREADS) m2_s[i] = g_m2[i];

    float rowmin[8];
#pragma unroll
    for (int k = 0; k < 8; ++k) rowmin[k] = 3.402823466e38f;

    // ---- mainloop: ONE barrier per tile ----
    // iter ct: wait(buf ct) -> sync -> prefetch(ct+1) -> MMA(ct) -> epilogue(ct)
    // The top sync both publishes buf[ct] and proves tile (ct-1) reads finished,
    // making the immediate prefetch into buf[(ct+1)&1] safe.
    for (int ct = 0; ct < NTILES; ++ct) {
        CP_WAIT(0);               // tile ct resident (committed >=1 tile ago)
        __syncthreads();
        if (ct + 1 < NTILES) {
            const uint4* src = g_mub[ct + 1];
            uint32_t dst = sb + B_W((ct + 1) & 1) * 4;
            for (int i = tid; i < BT_WORDS / 4; i += NTHREADS)
                cp_async16(dst + i * 16, src + i);
            CP_COMMIT();
        }

        float acc[4][4][4];
#pragma unroll
        for (int mt = 0; mt < 4; ++mt)
#pragma unroll
            for (int nt = 0; nt < 4; ++nt)
#pragma unroll
                for (int q = 0; q < 4; ++q) acc[mt][nt][q] = 0.f;

        const uint32_t* Bbuf = sm + B_W(ct & 1);
#pragma unroll
        for (int ks = 0; ks < 8; ++ks) {
            uint32_t a[4][4];
            uint4 bb[2];
#pragma unroll
            for (int mt = 0; mt < 4; ++mt)
                *reinterpret_cast<uint4*>(a[mt]) = *reinterpret_cast<const uint4*>(
                    &A_s[(((warp_m * 4 + mt) * 8 + ks) * 33 + lane) * 4]);
#pragma unroll
            for (int pr = 0; pr < 2; ++pr)
                bb[pr] = *reinterpret_cast<const uint4*>(
                    &Bbuf[(((warp_n * 2 + pr) * 8 + ks) * 32 + lane) * 4]);
#pragma unroll
            for (int mt = 0; mt < 4; ++mt) {
                mma_fp16(acc[mt][0], a[mt], bb[0].x, bb[0].y);
                mma_fp16(acc[mt][1], a[mt], bb[0].z, bb[0].w);
                mma_fp16(acc[mt][2], a[mt], bb[1].x, bb[1].y);
                mma_fp16(acc[mt][3], a[mt], bb[1].z, bb[1].w);
            }
        }

        // ---- epilogue: d2 = z2 + m2 - 2*dot, running min (no barrier) ----
        // D frag: c0=(g,2tig) c1=(g,2tig+1) c2=(g+8,2tig) c3=(g+8,2tig+1)
#pragma unroll
        for (int mt = 0; mt < 4; ++mt) {
            int rb = warp_m * 64 + mt * 16 + g;
            float z2a = z2_s[rb], z2b = z2_s[rb + 8];
#pragma unroll
            for (int nt = 0; nt < 4; ++nt) {
                int cb = ct * BN + warp_n * 32 + nt * 8 + 2 * tig;
                float m0 = m2_s[cb], m1 = m2_s[cb + 1];
                rowmin[mt * 2]     = fminf(rowmin[mt * 2],
                                           fmaf(-2.f, acc[mt][nt][0], z2a + m0));
                rowmin[mt * 2]     = fminf(rowmin[mt * 2],
                                           fmaf(-2.f, acc[mt][nt][1], z2a + m1));
                rowmin[mt * 2 + 1] = fminf(rowmin[mt * 2 + 1],
                                           fmaf(-2.f, acc[mt][nt][2], z2b + m0));
                rowmin[mt * 2 + 1] = fminf(rowmin[mt * 2 + 1],
                                           fmaf(-2.f, acc[mt][nt][3], z2b + m1));
            }
        }
    }

    // ---- min across 4 tig lanes, sqrt, sum within block ----
#pragma unroll
    for (int k = 0; k < 8; ++k) {
        float v = rowmin[k];
        v = fminf(v, __shfl_xor_sync(0xffffffffu, v, 1));
        v = fminf(v, __shfl_xor_sync(0xffffffffu, v, 2));
        rowmin[k] = v;
    }
    __syncthreads();              // B reads done before A_s reuse as red matrix
    float* red = reinterpret_cast<float*>(A_s);
    if (tig == 0) {
#pragma unroll
        for (int mt = 0; mt < 4; ++mt) {
            red[(warp_m * 64 + mt * 16 + g) * 4 + warp_n]     = rowmin[mt * 2];
            red[(warp_m * 64 + mt * 16 + 8 + g) * 4 + warp_n] = rowmin[mt * 2 + 1];
        }
    }
    __syncthreads();

    float dist = 0.f;
    if (tid < BM) {
        float m = fminf(fminf(red[tid * 4], red[tid * 4 + 1]),
                        fminf(red[tid * 4 + 2], red[tid * 4 + 3]));
        dist = sqrtf(fmaxf(m, 0.f));
    }
#pragma unroll
    for (int o = 16; o; o >>= 1) dist += __shfl_down_sync(0xffffffffu, dist, o);
    if (lane == 0) sh[w] = dist;
    __syncthreads();
    if (tid == 0) {
        float s = 0.f;
#pragma unroll
        for (int i = 0; i < 8; i++) s += sh[i];
        g_partials[blockIdx.x] = s;
    }
    __threadfence();

    // ---- fused deterministic final reduction: last block sums all partials ----
    __shared__ unsigned lastflag;
    if (tid == 0) lastflag = atomicInc(&g_done, NBLK - 1);  // wraps back to 0
    __syncthreads();
    if (lastflag == NBLK - 1) {
        __threadfence();
        float v = g_partials[tid] + g_partials[tid + NTHREADS];
#pragma unroll
        for (int o = 16; o; o >>= 1) v += __shfl_down_sync(0xffffffffu, v, o);
        if (lane == 0) sh[w] = v;
        __syncthreads();
        if (tid == 0) {
            float s = 0.f;
#pragma unroll
            for (int i = 0; i < 8; i++) s += sh[i];
            out[0] = s / (float)NROWS;
        }
    }
}

// ---------------------------------------------------------------------------
extern "C" void kernel_launch(void* const* d_in, const int* in_sizes, int n_in,
                              void* d_out, int out_size) {
    const float* z  = (const float*)d_in[0];   // (65536,1,128) contiguous
    const float* mu = (const float*)d_in[1];   // (512,128)
    float* out = (float*)d_out;

    cudaFuncSetAttribute(kmeans_mma_kernel,
                         cudaFuncAttributeMaxDynamicSharedMemorySize, SMEM_BYTES);

    mu_prep_kernel<<<NTILES * 8, 256>>>(mu);
    kmeans_mma_kernel<<<NBLK, NTHREADS, SMEM_BYTES>>>(z, out);
}